// round 4
// baseline (speedup 1.0000x reference)
#include <cuda_runtime.h>

#define NTOK 4096
#define CDIM 256
#define NH   8
#define HD   32
#define SCALE 0.17677669529663687f   // 1/sqrt(32)

#define BQ 128
#define BK 64

typedef unsigned long long u64;

// ---- f32x2 packed-math helpers (Blackwell double-pumped fp32) ----
__device__ __forceinline__ u64 bcast2(float v) {
    u64 r; asm("mov.b64 %0, {%1, %1};" : "=l"(r) : "f"(v)); return r;
}
__device__ __forceinline__ float2 unpk2(u64 v) {
    float2 f; asm("mov.b64 {%0, %1}, %2;" : "=f"(f.x), "=f"(f.y) : "l"(v)); return f;
}
__device__ __forceinline__ void ffma2(u64& d, u64 a, u64 b) {
    asm("fma.rn.f32x2 %0, %1, %2, %0;" : "+l"(d) : "l"(a), "l"(b));
}
__device__ __forceinline__ void fmul2(u64& d, u64 a) {
    asm("mul.rn.f32x2 %0, %0, %1;" : "+l"(d) : "l"(a));
}

// scratch (device globals: no allocation allowed)
__device__ float g_Qt[NH*HD*NTOK];   // Q transposed per head: [h][d][n], pre-scaled
__device__ float g_Kt[NH*HD*NTOK];   // K transposed per head: [h][d][n]
__device__ float g_V [NH*NTOK*HD];   // V: [h][n][d]
__device__ float g_T [NTOK*CDIM];    // attention output tokens [n][c]

// ---------------------------------------------------------------------------
// Kernel 1: QKV = tok @ qkv_w^T ; tok[n][c] = x[c][n]
// ---------------------------------------------------------------------------
__global__ __launch_bounds__(256) void qkv_kernel(const float* __restrict__ x,
                                                  const float* __restrict__ w) {
    __shared__ float As[16][64];   // [k][n-local]
    __shared__ float Bs[16][68];   // [k][o-local], padded (272B rows, 16B-aligned cells)
    const int n0 = blockIdx.x * 64;
    const int o0 = blockIdx.y * 64;
    const int tid = threadIdx.x;
    const int tx = tid & 15, ty = tid >> 4;

    u64 acc2[2][4] = {};                               // row-pairs (n) x 4 cols (o)
    const int li = tid & 63, lk = tid >> 6;
    const int bj = tid >> 2, bk4 = (tid & 3) * 4;

    for (int c0 = 0; c0 < 256; c0 += 16) {
        #pragma unroll
        for (int kk = 0; kk < 4; kk++)
            As[lk + kk*4][li] = x[(c0 + lk + kk*4) * NTOK + n0 + li];
        float4 wb = *(const float4*)(w + (o0 + bj) * 256 + c0 + bk4);
        Bs[bk4+0][bj] = wb.x; Bs[bk4+1][bj] = wb.y;
        Bs[bk4+2][bj] = wb.z; Bs[bk4+3][bj] = wb.w;
        __syncthreads();
        #pragma unroll
        for (int k = 0; k < 16; k++) {
            ulonglong2 ap = *(const ulonglong2*)(&As[k][ty*4]);  // pairs {a0,a1},{a2,a3}
            float4 b = *(const float4*)(&Bs[k][tx*4]);
            u64 aq[2] = {ap.x, ap.y};
            u64 bb[4] = {bcast2(b.x), bcast2(b.y), bcast2(b.z), bcast2(b.w)};
            #pragma unroll
            for (int up = 0; up < 2; up++)
                #pragma unroll
                for (int v = 0; v < 4; v++)
                    ffma2(acc2[up][v], aq[up], bb[v]);
        }
        __syncthreads();
    }

    #pragma unroll
    for (int up = 0; up < 2; up++) {
        #pragma unroll
        for (int v = 0; v < 4; v++) {
            float2 f = unpk2(acc2[up][v]);
            const int o = o0 + tx*4 + v;
            const int t = o >> 8, hh = (o >> 5) & 7, d = o & 31;
            #pragma unroll
            for (int s = 0; s < 2; s++) {
                const int n = n0 + ty*4 + up*2 + s;
                const float val = s ? f.y : f.x;
                if (t == 0)      g_Qt[(hh*HD + d)*NTOK + n] = val * SCALE;
                else if (t == 1) g_Kt[(hh*HD + d)*NTOK + n] = val;
                else             g_V [(hh*NTOK + n)*HD + d] = val;
            }
        }
    }
}

// ---------------------------------------------------------------------------
// Kernel 2: masked flash attention. One block = (128 queries, 1 head).
// Mask: integer dist^2 <= 99  (exact form of dist < 10 on integer coords).
// ---------------------------------------------------------------------------
#define PS_STRIDE 66
#define VS_STRIDE 36
#define ATTN_SMEM_FLOATS (32*128 + 32*64 + 64*VS_STRIDE + 128*PS_STRIDE + 256)

__global__ __launch_bounds__(256, 2) void attn_kernel() {
    extern __shared__ float sm[];
    float* Qt  = sm;                       // [k][r]   32 x 128
    float* Kt  = Qt + 32*128;              // [k][c]   32 x 64
    float* Vs  = Kt + 32*64;               // [m][d]   64 x 36(pad, 144B rows)
    float* Ps  = Vs + 64*VS_STRIDE;        // [r][m]  128 x 66(pad)
    float* alp = Ps + 128*PS_STRIDE;       // [128]
    float* lro = alp + 128;                // [128]

    const int tid = threadIdx.x;
    const int h  = blockIdx.y;
    const int n0 = blockIdx.x * BQ;
    const int zq  = n0 >> 8;
    const int y0q = (n0 >> 4) & 15;

    // score-phase mapping: 16x16 grid, each thread 8 rows x 4 cols
    const int tx = tid & 15, ty = tid >> 4;
    const int r0 = ty * 8, c0 = tx * 4;
    // AV-phase mapping: 64x4 grid, each thread 2 rows x 8 dims
    const int rg = tid >> 2, cg = tid & 3;
    const int ra = rg * 2, d0 = cg * 8;

    const float* gq = g_Qt + h*HD*NTOK;
    const float* gk = g_Kt + h*HD*NTOK;
    const float* gv = g_V  + h*NTOK*HD;

    for (int idx = tid; idx < 32*128; idx += 256) {
        const int k = idx >> 7, r = idx & 127;
        Qt[idx] = gq[k*NTOK + n0 + r];
    }

    float mreg[8], lreg[8];
    #pragma unroll
    for (int u = 0; u < 8; u++) { mreg[u] = -1e30f; lreg[u] = 0.f; }
    u64 O2[2][4] = {};   // 2 rows x 4 dim-pairs (8 dims)

    int yq[8], xq[8];
    #pragma unroll
    for (int u = 0; u < 8; u++) {
        const int nq = n0 + r0 + u;
        yq[u] = (nq >> 4) & 15;
        xq[u] = nq & 15;
    }

    const int zlo = max(0, zq - 9), zhi = min(15, zq + 9);
    __syncthreads();

    for (int m0 = zlo*256; m0 <= zhi*256 + 192; m0 += BK) {
        const int zk = m0 >> 8;
        const int dz = zq - zk;
        const int y0k = (m0 >> 4) & 15;
        const int gap = max(0, max(y0k - (y0q + 7), y0q - (y0k + 3)));
        if (dz*dz + gap*gap > 99) continue;   // whole key tile masked

        for (int idx = tid; idx < 32*64; idx += 256)
            Kt[idx] = gk[(idx >> 6)*NTOK + m0 + (idx & 63)];
        for (int idx = tid; idx < 64*32; idx += 256) {
            const int m = idx >> 5, d = idx & 31;
            Vs[m*VS_STRIDE + d] = gv[(m0 + m)*HD + d];
        }
        __syncthreads();

        // ---- scores S = Q K^T, f32x2 packed along row pairs ----
        u64 acc2[4][4] = {};
        #pragma unroll 8
        for (int k = 0; k < 32; k++) {
            ulonglong2 qa = *(const ulonglong2*)(Qt + k*128 + r0);      // rows (0,1),(2,3)
            ulonglong2 qb = *(const ulonglong2*)(Qt + k*128 + r0 + 4);  // rows (4,5),(6,7)
            float4 kv = *(const float4*)(Kt + k*64 + c0);
            u64 qq[4] = {qa.x, qa.y, qb.x, qb.y};
            u64 kb[4] = {bcast2(kv.x), bcast2(kv.y), bcast2(kv.z), bcast2(kv.w)};
            #pragma unroll
            for (int up = 0; up < 4; up++)
                #pragma unroll
                for (int v = 0; v < 4; v++)
                    ffma2(acc2[up][v], qq[up], kb[v]);
        }
        float acc[8][4];
        #pragma unroll
        for (int up = 0; up < 4; up++)
            #pragma unroll
            for (int v = 0; v < 4; v++) {
                float2 f = unpk2(acc2[up][v]);
                acc[2*up][v]   = f.x;
                acc[2*up+1][v] = f.y;
            }

        // ---- mask + online softmax ----
        const int thr = 99 - dz*dz;
        int yk[4], xk[4];
        #pragma unroll
        for (int v = 0; v < 4; v++) {
            const int mk = m0 + c0 + v;
            yk[v] = (mk >> 4) & 15;
            xk[v] = mk & 15;
        }
        #pragma unroll
        for (int u = 0; u < 8; u++) {
            float tmax = -1e30f;
            #pragma unroll
            for (int v = 0; v < 4; v++) {
                const int dy = yq[u] - yk[v];
                const int dx = xq[u] - xk[v];
                if (dy*dy + dx*dx > thr) acc[u][v] = -1e30f;
                tmax = fmaxf(tmax, acc[u][v]);
            }
            #pragma unroll
            for (int off = 8; off; off >>= 1)
                tmax = fmaxf(tmax, __shfl_xor_sync(0xffffffffu, tmax, off));
            const float mnew = fmaxf(mreg[u], tmax);
            const float a = __expf(mreg[u] - mnew);
            float psum = 0.f;
            #pragma unroll
            for (int v = 0; v < 4; v++) {
                // masked rows (-1e30) must give p==0 even when mnew==-1e30
                const float p = (acc[u][v] < -1e29f) ? 0.f : __expf(acc[u][v] - mnew);
                Ps[(r0+u)*PS_STRIDE + c0 + v] = p;
                psum += p;
            }
            #pragma unroll
            for (int off = 8; off; off >>= 1)
                psum += __shfl_xor_sync(0xffffffffu, psum, off);
            lreg[u] = lreg[u]*a + psum;
            mreg[u] = mnew;
            if (tx == 0) alp[r0+u] = a;
        }
        __syncthreads();

        // ---- O = alpha*O + P V  (f32x2 packed along dim pairs) ----
        {
            u64 a0 = bcast2(alp[ra]), a1 = bcast2(alp[ra+1]);
            #pragma unroll
            for (int j = 0; j < 4; j++) { fmul2(O2[0][j], a0); fmul2(O2[1][j], a1); }
        }
        #pragma unroll 4
        for (int m = 0; m < BK; m++) {
            ulonglong2 va = *(const ulonglong2*)(Vs + m*VS_STRIDE + d0);
            ulonglong2 vb = *(const ulonglong2*)(Vs + m*VS_STRIDE + d0 + 4);
            u64 vv[4] = {va.x, va.y, vb.x, vb.y};
            u64 p0 = bcast2(Ps[(ra  )*PS_STRIDE + m]);
            u64 p1 = bcast2(Ps[(ra+1)*PS_STRIDE + m]);
            #pragma unroll
            for (int j = 0; j < 4; j++) {
                ffma2(O2[0][j], p0, vv[j]);
                ffma2(O2[1][j], p1, vv[j]);
            }
        }
        __syncthreads();
    }

    if (tx == 0) {
        #pragma unroll
        for (int u = 0; u < 8; u++) lro[r0+u] = lreg[u];
    }
    __syncthreads();

    #pragma unroll
    for (int u = 0; u < 2; u++) {
        const float inv = 1.0f / lro[ra + u];
        float res[8];
        #pragma unroll
        for (int j = 0; j < 4; j++) {
            float2 f = unpk2(O2[u][j]);
            res[2*j]   = f.x * inv;
            res[2*j+1] = f.y * inv;
        }
        float* dst = g_T + (n0 + ra + u)*CDIM + h*HD + d0;
        *(float4*)(dst)     = make_float4(res[0], res[1], res[2], res[3]);
        *(float4*)(dst + 4) = make_float4(res[4], res[5], res[6], res[7]);
    }
}

// ---------------------------------------------------------------------------
// Kernel 3: out[o][n] = sum_c T[n][c] * proj_w[o][c] + b[o]   (output [C,N])
// ---------------------------------------------------------------------------
__global__ __launch_bounds__(256) void proj_kernel(const float* __restrict__ w,
                                                   const float* __restrict__ bias,
                                                   float* __restrict__ out) {
    __shared__ float Ws[16][68];   // [k][o-local]
    __shared__ float Ts[16][68];   // [k][n-local]
    const int n0 = blockIdx.x * 64;
    const int o0 = blockIdx.y * 64;
    const int tid = threadIdx.x;
    const int tx = tid & 15, ty = tid >> 4;

    u64 acc2[2][4] = {};                               // o-row pairs x 4 n-cols
    const int j = tid >> 2, k4 = (tid & 3) * 4;

    for (int c0 = 0; c0 < 256; c0 += 16) {
        float4 wv = *(const float4*)(w   + (o0 + j)*256 + c0 + k4);
        Ws[k4+0][j]=wv.x; Ws[k4+1][j]=wv.y; Ws[k4+2][j]=wv.z; Ws[k4+3][j]=wv.w;
        float4 tv = *(const float4*)(g_T + (n0 + j)*256 + c0 + k4);
        Ts[k4+0][j]=tv.x; Ts[k4+1][j]=tv.y; Ts[k4+2][j]=tv.z; Ts[k4+3][j]=tv.w;
        __syncthreads();
        #pragma unroll
        for (int k = 0; k < 16; k++) {
            ulonglong2 ap = *(const ulonglong2*)(&Ws[k][ty*4]);
            float4 b = *(const float4*)(&Ts[k][tx*4]);
            u64 aq[2] = {ap.x, ap.y};
            u64 bb[4] = {bcast2(b.x), bcast2(b.y), bcast2(b.z), bcast2(b.w)};
            #pragma unroll
            for (int up = 0; up < 2; up++)
                #pragma unroll
                for (int v = 0; v < 4; v++)
                    ffma2(acc2[up][v], aq[up], bb[v]);
        }
        __syncthreads();
    }

    #pragma unroll
    for (int up = 0; up < 2; up++) {
        #pragma unroll
        for (int s = 0; s < 2; s++) {
            const int o = o0 + ty*4 + up*2 + s;
            const float bo = bias[o];
            float r[4];
            #pragma unroll
            for (int v = 0; v < 4; v++) {
                float2 f = unpk2(acc2[up][v]);
                r[v] = (s ? f.y : f.x) + bo;
            }
            *(float4*)(out + (size_t)o*NTOK + n0 + tx*4) =
                make_float4(r[0], r[1], r[2], r[3]);
        }
    }
}

// ---------------------------------------------------------------------------
extern "C" void kernel_launch(void* const* d_in, const int* in_sizes, int n_in,
                              void* d_out, int out_size) {
    const float *x = nullptr, *wq = nullptr, *wp = nullptr, *bp = nullptr;
    for (int i = 0; i < n_in; i++) {
        switch (in_sizes[i]) {
            case 1048576: x  = (const float*)d_in[i]; break;  // x [1,256,16,16,16]
            case 196608:  wq = (const float*)d_in[i]; break;  // qkv_w [768,256]
            case 65536:   wp = (const float*)d_in[i]; break;  // proj_w [256,256]
            case 256:     bp = (const float*)d_in[i]; break;  // proj_b [256]
        }
    }
    float* out = (float*)d_out;

    cudaFuncSetAttribute(attn_kernel, cudaFuncAttributeMaxDynamicSharedMemorySize,
                         ATTN_SMEM_FLOATS * (int)sizeof(float));

    qkv_kernel <<<dim3(NTOK/64, 768/64), 256>>>(x, wq);
    attn_kernel<<<dim3(NTOK/BQ, NH), 256, ATTN_SMEM_FLOATS * (int)sizeof(float)>>>();
    proj_kernel<<<dim3(NTOK/64, CDIM/64), 256>>>(wp, bp, out);
}